// round 1
// baseline (speedup 1.0000x reference)
#include <cuda_runtime.h>

// ----------------------------------------------------------------------------
// BagModel: out[b] = mean_{i in bag b}( relu(x_i @ W1 + b1) @ W2 ) + b2
// Exploits linearity of @W2 after relu: reduce each instance to a scalar first.
// ----------------------------------------------------------------------------

#define MAX_BAGS (1 << 18)   // 262144 >= 100000 bags

__device__ float g_sum[MAX_BAGS];
__device__ float g_cnt[MAX_BAGS];

// Zero the segment-sum scratch (must be re-zeroed every launch: graph replays).
__global__ void zero_kernel(int nbags) {
    int i = blockIdx.x * blockDim.x + threadIdx.x;
    if (i < nbags) {
        g_sum[i] = 0.0f;
        g_cnt[i] = 0.0f;
    }
}

// Main kernel: one thread per instance.
// s_i = sum_j relu( b1[j] + sum_k x[i,k]*W1[k,j] ) * W2[j]
// then atomic segment-sum of s_i and count into g_sum/g_cnt keyed by ids[i].
__global__ __launch_bounds__(256) void mlp_scalar_kernel(
    const float* __restrict__ x,     // [n, 32]
    const int*   __restrict__ ids,   // [n]
    const float* __restrict__ W1,    // [32, 64] row-major (k-major)
    const float* __restrict__ b1,    // [64]
    const float* __restrict__ W2,    // [64]
    int n)
{
    __shared__ float sW1[32 * 64];   // 8 KB, row k contiguous in j
    __shared__ float sb1[64];
    __shared__ float sW2[64];

    for (int i = threadIdx.x; i < 32 * 64; i += 256) sW1[i] = W1[i];
    if (threadIdx.x < 64) {
        sb1[threadIdx.x] = b1[threadIdx.x];
        sW2[threadIdx.x] = W2[threadIdx.x];
    }
    __syncthreads();

    int i = blockIdx.x * blockDim.x + threadIdx.x;
    if (i >= n) return;

    // Load this instance's 32 inputs (8 x LDG.128).
    float xv[32];
    const float4* xp = reinterpret_cast<const float4*>(x + (size_t)i * 32);
    #pragma unroll
    for (int q = 0; q < 8; q++) {
        float4 v = xp[q];
        xv[4 * q + 0] = v.x;
        xv[4 * q + 1] = v.y;
        xv[4 * q + 2] = v.z;
        xv[4 * q + 3] = v.w;
    }

    float s = 0.0f;
    // 16 blocks of 4 hidden units; each block: 32 LDS.128 (uniform/broadcast)
    // + 128 FFMA across 4 independent accumulator chains.
    for (int jb = 0; jb < 16; jb++) {
        float a0 = sb1[4 * jb + 0];
        float a1 = sb1[4 * jb + 1];
        float a2 = sb1[4 * jb + 2];
        float a3 = sb1[4 * jb + 3];
        #pragma unroll
        for (int k = 0; k < 32; k++) {
            float4 w = *reinterpret_cast<const float4*>(sW1 + k * 64 + jb * 4);
            a0 = fmaf(xv[k], w.x, a0);
            a1 = fmaf(xv[k], w.y, a1);
            a2 = fmaf(xv[k], w.z, a2);
            a3 = fmaf(xv[k], w.w, a3);
        }
        s = fmaf(fmaxf(a0, 0.0f), sW2[4 * jb + 0], s);
        s = fmaf(fmaxf(a1, 0.0f), sW2[4 * jb + 1], s);
        s = fmaf(fmaxf(a2, 0.0f), sW2[4 * jb + 2], s);
        s = fmaf(fmaxf(a3, 0.0f), sW2[4 * jb + 3], s);
    }

    int bag = ids[i];
    atomicAdd(&g_sum[bag], s);
    atomicAdd(&g_cnt[bag], 1.0f);
}

// Finalize: out[b] = g_sum[b]/g_cnt[b] + b2[0]
__global__ void finalize_kernel(float* __restrict__ out,
                                const float* __restrict__ b2,
                                int nbags)
{
    int b = blockIdx.x * blockDim.x + threadIdx.x;
    if (b < nbags) {
        float c = g_cnt[b];
        c = (c > 0.0f) ? c : 1.0f;   // every bag present per reference; guard anyway
        out[b] = g_sum[b] / c + b2[0];
    }
}

extern "C" void kernel_launch(void* const* d_in, const int* in_sizes, int n_in,
                              void* d_out, int out_size)
{
    // Input order per metadata: x, ids, W1, b1, W2, b2
    const float* x   = (const float*)d_in[0];
    const int*   ids = (const int*)  d_in[1];
    const float* W1  = (const float*)d_in[2];
    const float* b1  = (const float*)d_in[3];
    const float* W2  = (const float*)d_in[4];
    const float* b2  = (const float*)d_in[5];
    float* out = (float*)d_out;

    int n     = in_sizes[1];   // number of instances (ids element count)
    int nbags = out_size;      // D_OUT == 1, so out_size == NUM_BAGS

    zero_kernel<<<(nbags + 255) / 256, 256>>>(nbags);
    mlp_scalar_kernel<<<(n + 255) / 256, 256>>>(x, ids, W1, b1, W2, n);
    finalize_kernel<<<(nbags + 255) / 256, 256>>>(out, b2, nbags);
}

// round 4
// speedup vs baseline: 1.5725x; 1.5725x over previous
#include <cuda_runtime.h>
#include <mma.h>
#include <cstdint>

using namespace nvcuda;

// ----------------------------------------------------------------------------
// BagModel via wmma tf32 (m16n16k8) — compiler-managed fragment layouts:
//   per 128-row tile: D = X[128,32] @ W1[32,64]  (tf32 in, fp32 accum)
//   epilogue: acc tile -> SMEM -> per-row s = sum_j relu(D[r,j]+b1[j])*W2[j]
//   segment mean via atomics; finalize out = sum/cnt + b2.
// ----------------------------------------------------------------------------

#define MAX_BAGS (1 << 18)
__device__ float g_sum[MAX_BAGS];
__device__ float g_cnt[MAX_BAGS];

__global__ void zero_kernel(int nbags) {
    int i = blockIdx.x * blockDim.x + threadIdx.x;
    if (i < nbags) { g_sum[i] = 0.0f; g_cnt[i] = 0.0f; }
}

static constexpr int LDA = 36;   // 128 x 32 A tile, padded row stride
static constexpr int LDB = 68;   // 32 x 64 B tile, padded row stride
static constexpr int LDD = 20;   // 16 x 16 per-warp D scratch, padded (mult of 4)

__global__ __launch_bounds__(128) void mlp_wmma_kernel(
    const float* __restrict__ x,     // [n, 32]
    const int*   __restrict__ ids,   // [n]
    const float* __restrict__ W1,    // [32, 64]
    const float* __restrict__ b1,    // [64]
    const float* __restrict__ W2,    // [64]
    int n, int ntiles)
{
    __shared__ __align__(16) float sA[128 * LDA];
    __shared__ __align__(16) float sB[32 * LDB];
    __shared__ __align__(16) float sD[4][16 * LDD];
    __shared__ float2 sBW[64];

    const int tid  = threadIdx.x;
    const int lane = tid & 31;
    const int warp = tid >> 5;

    // one-time: W1 -> sB (tf32 values), (b1, W2) pairs
    for (int idx = tid; idx < 32 * 64; idx += 128) {
        int k = idx >> 6, nn = idx & 63;
        sB[k * LDB + nn] = wmma::__float_to_tf32(W1[k * 64 + nn]);
    }
    if (tid < 64) sBW[tid] = make_float2(b1[tid], W2[tid]);
    __syncthreads();

    const float4* xg = reinterpret_cast<const float4*>(x);
    const int r16  = lane & 15;      // row within 16-row tile
    const int half = lane >> 4;      // column half (0: cols 0-7, 1: cols 8-15)

    for (int tile = blockIdx.x; tile < ntiles; tile += gridDim.x) {
        const int row0 = tile * 128;

        // stage X tile: coalesced LDG.128, tf32-convert, STS.128
        #pragma unroll
        for (int tt = 0; tt < 8; tt++) {
            int idx = tid + tt * 128;            // 0..1023 float4 slots
            int row = idx >> 3, q = idx & 7;
            float4 v = make_float4(0.f, 0.f, 0.f, 0.f);
            if (row0 + row < n) v = xg[(size_t)tile * 1024 + idx];
            v.x = wmma::__float_to_tf32(v.x);
            v.y = wmma::__float_to_tf32(v.y);
            v.z = wmma::__float_to_tf32(v.z);
            v.w = wmma::__float_to_tf32(v.w);
            *reinterpret_cast<float4*>(sA + row * LDA + q * 4) = v;
        }
        __syncthreads();

        // GEMM: warp covers rows [warp*32, warp*32+32), all 64 columns
        wmma::fragment<wmma::accumulator, 16, 16, 8, float> acc[2][4];
        #pragma unroll
        for (int mt = 0; mt < 2; mt++)
            #pragma unroll
            for (int nt = 0; nt < 4; nt++)
                wmma::fill_fragment(acc[mt][nt], 0.0f);

        #pragma unroll
        for (int k = 0; k < 4; k++) {
            wmma::fragment<wmma::matrix_a, 16, 16, 8, wmma::precision::tf32,
                           wmma::row_major> af[2];
            wmma::load_matrix_sync(af[0], sA + (warp * 32 +  0) * LDA + k * 8, LDA);
            wmma::load_matrix_sync(af[1], sA + (warp * 32 + 16) * LDA + k * 8, LDA);
            #pragma unroll
            for (int nt = 0; nt < 4; nt++) {
                wmma::fragment<wmma::matrix_b, 16, 16, 8, wmma::precision::tf32,
                               wmma::row_major> bf;
                wmma::load_matrix_sync(bf, sB + (k * 8) * LDB + nt * 16, LDB);
                wmma::mma_sync(acc[0][nt], af[0], bf, acc[0][nt]);
                wmma::mma_sync(acc[1][nt], af[1], bf, acc[1][nt]);
            }
        }

        // epilogue: per acc tile, roundtrip through SMEM (layout-safe),
        // then per-row relu + W2 reduction.
        float srow[2] = {0.0f, 0.0f};
        #pragma unroll
        for (int mt = 0; mt < 2; mt++) {
            #pragma unroll
            for (int nt = 0; nt < 4; nt++) {
                wmma::store_matrix_sync(&sD[warp][0], acc[mt][nt], LDD,
                                        wmma::mem_row_major);
                __syncwarp();
                #pragma unroll
                for (int c = 0; c < 8; c++) {
                    int j = nt * 16 + half * 8 + c;
                    float v = sD[warp][r16 * LDD + half * 8 + c];
                    float2 bw = sBW[j];
                    srow[mt] = fmaf(fmaxf(v + bw.x, 0.0f), bw.y, srow[mt]);
                }
                __syncwarp();
            }
        }
        srow[0] += __shfl_xor_sync(0xFFFFFFFF, srow[0], 16);
        srow[1] += __shfl_xor_sync(0xFFFFFFFF, srow[1], 16);

        if (lane < 16) {
            #pragma unroll
            for (int mt = 0; mt < 2; mt++) {
                int rr = row0 + warp * 32 + mt * 16 + r16;
                if (rr < n) {
                    int bag = ids[rr];
                    atomicAdd(&g_sum[bag], srow[mt]);
                    atomicAdd(&g_cnt[bag], 1.0f);
                }
            }
        }
        __syncthreads();   // sA reusable next iteration
    }
}

__global__ void finalize_kernel(float* __restrict__ out,
                                const float* __restrict__ b2, int nbags)
{
    int b = blockIdx.x * blockDim.x + threadIdx.x;
    if (b < nbags) {
        float c = g_cnt[b];
        c = (c > 0.0f) ? c : 1.0f;
        out[b] = g_sum[b] / c + b2[0];
    }
}

extern "C" void kernel_launch(void* const* d_in, const int* in_sizes, int n_in,
                              void* d_out, int out_size)
{
    const float* x   = (const float*)d_in[0];
    const int*   ids = (const int*)  d_in[1];
    const float* W1  = (const float*)d_in[2];
    const float* b1  = (const float*)d_in[3];
    const float* W2  = (const float*)d_in[4];
    const float* b2  = (const float*)d_in[5];
    float* out = (float*)d_out;

    int n      = in_sizes[1];
    int nbags  = out_size;
    int ntiles = (n + 127) / 128;

    zero_kernel<<<(nbags + 255) / 256, 256>>>(nbags);

    int grid = 148 * 7;
    if (grid > ntiles) grid = ntiles;
    mlp_wmma_kernel<<<grid, 128>>>(x, ids, W1, b1, W2, n, ntiles);

    finalize_kernel<<<(nbags + 255) / 256, 256>>>(out, b2, nbags);
}